// round 8
// baseline (speedup 1.0000x reference)
#include <cuda_runtime.h>
#include <math.h>
#include <stdint.h>

#define T_TOKENS 2048
#define HID      1024
#define INTER    2048
#define NEXP     8
#define NPAIRS   (T_TOKENS * 2)

// ---------------- scratch -----------------------------------------------------
__device__ int   g_counts[NEXP];
__device__ int   g_pairs[NEXP * NPAIRS];
__device__ float g_w[NPAIRS];
__device__ float g_inter[(size_t)NPAIRS * INTER];          // 32 MB (tf32-rounded)
__device__ float g_xt[(size_t)T_TOKENS * HID];             // 8 MB  x in tf32
__device__ float g_w0t[(size_t)NEXP * INTER * HID];        // 64 MB wi0^T tf32 [e][n][k]
__device__ float g_w1t[(size_t)NEXP * INTER * HID];        // 64 MB wi1^T tf32
__device__ float g_wot[(size_t)NEXP * HID * INTER];        // 64 MB wo^T  tf32 [e][n][k]

// ---------------- helpers -------------------------------------------------------
__device__ __forceinline__ float tf(float f) {
    uint32_t r;
    asm("cvt.rna.tf32.f32 %0, %1;" : "=r"(r) : "f"(f));
    return __uint_as_float(r);
}
__device__ __forceinline__ uint32_t smem_u32(const void* p) {
    uint32_t a;
    asm("{ .reg .u64 t; cvta.to.shared.u64 t, %1; cvt.u32.u64 %0, t; }" : "=r"(a) : "l"(p));
    return a;
}
__device__ __forceinline__ void mma8(float* d, const uint32_t* a, const uint32_t* b) {
    asm volatile(
        "mma.sync.aligned.m16n8k8.row.col.f32.tf32.tf32.f32 "
        "{%0,%1,%2,%3}, {%4,%5,%6,%7}, {%8,%9}, {%0,%1,%2,%3};"
        : "+f"(d[0]), "+f"(d[1]), "+f"(d[2]), "+f"(d[3])
        : "r"(a[0]), "r"(a[1]), "r"(a[2]), "r"(a[3]), "r"(b[0]), "r"(b[1]));
}
__device__ __forceinline__ void ldsm4(uint32_t* r, uint32_t addr) {
    asm volatile("ldmatrix.sync.aligned.m8n8.x4.shared.b16 {%0,%1,%2,%3}, [%4];"
        : "=r"(r[0]), "=r"(r[1]), "=r"(r[2]), "=r"(r[3]) : "r"(addr));
}
__device__ __forceinline__ void cpa(uint32_t dst, const void* src) {
    asm volatile("cp.async.cg.shared.global [%0], [%1], 16;" :: "r"(dst), "l"(src));
}
__device__ __forceinline__ void cpa_z(uint32_t dst, const void* src, uint32_t sz) {
    asm volatile("cp.async.cg.shared.global [%0], [%1], 16, %2;" :: "r"(dst), "l"(src), "r"(sz));
}
#define CP_COMMIT() asm volatile("cp.async.commit_group;" ::: "memory")
#define CP_WAIT1()  asm volatile("cp.async.wait_group 1;" ::: "memory")

// ---------------- routing --------------------------------------------------------
__global__ void zero_counts_kernel() {
    if (threadIdx.x < NEXP) g_counts[threadIdx.x] = 0;
}

__global__ void route_kernel(const float* __restrict__ logits) {
    int t = blockIdx.x * blockDim.x + threadIdx.x;
    if (t >= T_TOKENS) return;
    float l[NEXP];
#pragma unroll
    for (int e = 0; e < NEXP; e++) l[e] = logits[t * NEXP + e];
    int i0 = 0; float v0 = l[0];
#pragma unroll
    for (int e = 1; e < NEXP; e++) if (l[e] > v0) { v0 = l[e]; i0 = e; }
    int i1 = -1; float v1 = -__FLT_MAX__;
#pragma unroll
    for (int e = 0; e < NEXP; e++) {
        if (e == i0) continue;
        if (l[e] > v1) { v1 = l[e]; i1 = e; }
    }
    float e1 = expf(v1 - v0);
    float s  = 1.0f + e1;
    g_w[t * 2 + 0] = 1.0f / s;
    g_w[t * 2 + 1] = e1 / s;
    int p0 = atomicAdd(&g_counts[i0], 1);
    g_pairs[i0 * NPAIRS + p0] = t * 2 + 0;
    int p1 = atomicAdd(&g_counts[i1], 1);
    g_pairs[i1 * NPAIRS + p1] = t * 2 + 1;
}

__global__ void zero_out_kernel(float* __restrict__ out) {
    int i = blockIdx.x * blockDim.x + threadIdx.x;
    ((float4*)out)[i] = make_float4(0.f, 0.f, 0.f, 0.f);
}

// ---------------- pre-pass: convert x, convert+transpose weights ------------------
__global__ void convert_x_kernel(const float* __restrict__ x) {
    int i = blockIdx.x * blockDim.x + threadIdx.x;
    float4 v = ((const float4*)x)[i];
    ((float4*)g_xt)[i] = make_float4(tf(v.x), tf(v.y), tf(v.z), tf(v.w));
}

// in: [E][R][C] row-major; out: [E][C][R] tf32. blockDim (32,8).
__global__ void tconv_kernel(const float* __restrict__ in, float* __restrict__ out,
                             int R, int C) {
    __shared__ float t[32][33];
    const float* ip = in  + (size_t)blockIdx.z * R * C;
    float*       op = out + (size_t)blockIdx.z * R * C;
    int c0 = blockIdx.x * 32, r0 = blockIdx.y * 32;
    int tx = threadIdx.x, ty = threadIdx.y;
#pragma unroll
    for (int i = 0; i < 4; i++)
        t[ty + i * 8][tx] = tf(ip[(size_t)(r0 + ty + i * 8) * C + c0 + tx]);
    __syncthreads();
#pragma unroll
    for (int i = 0; i < 4; i++)
        op[(size_t)(c0 + ty + i * 8) * R + r0 + tx] = t[tx][ty + i * 8];
}

// ---------------- GEMM1: x @ {wi0, wi1}[e] + fused SwiGLU ------------------------
// CTA 128M x 128N (per matrix); k-chunk 32; 3-stage cp.async pipeline; SW128 smem.
// Stage s: A @ s*49152, B0 @ +16384, B1 @ +32768.
__global__ __launch_bounds__(256, 1) void gemm1_mma(const float* __restrict__ dummy)
{
    const int e   = blockIdx.z;
    const int cnt = g_counts[e];
    const int m0  = blockIdx.y * 128;
    if (m0 >= cnt) return;
    const int n0  = blockIdx.x * 128;

    extern __shared__ float smf[];
    unsigned char* smc = (unsigned char*)smf;
    const uint32_t sb = smem_u32(smc);

    const int tid = threadIdx.x, lane = tid & 31, wid = tid >> 5;
    const int wm = wid >> 2, wn = wid & 3;
    const int gq = lane >> 2, tg = lane & 3;
    const int l7 = lane & 7;

    const uint32_t aLane = (uint32_t)(wm * 64 + l7 + ((lane >> 3) & 1) * 8) * 128u;
    const int      c4a   = lane >> 4;
    const uint32_t bLane = (uint32_t)(wn * 32 + ((lane >> 4) & 1) * 8 + l7) * 128u;
    const int      c4b   = (lane >> 3) & 1;

    // per-thread copy mapping: row = tid>>1, chunks [half*4, half*4+4)
    const int row = tid >> 1, half = tid & 1;
    const float* arow;
    uint32_t asz;
    {
        int mg = m0 + row;
        if (mg < cnt) { arow = g_xt + (size_t)(g_pairs[e * NPAIRS + mg] >> 1) * HID; asz = 16u; }
        else          { arow = g_xt; asz = 0u; }
    }
    const float* b0row = g_w0t + (size_t)e * INTER * HID + (size_t)(n0 + row) * HID;
    const float* b1row = g_w1t + (size_t)e * INTER * HID + (size_t)(n0 + row) * HID;

    const uint32_t dBase = (uint32_t)row * 128u;

    auto issue_stage = [&](int s, int k0) {
        const uint32_t st = sb + (uint32_t)s * 49152u;
#pragma unroll
        for (int q = 0; q < 4; q++) {
            int cchunk = half * 4 + q;
            uint32_t doff = dBase + (uint32_t)((cchunk ^ (row & 7)) << 4);
            cpa_z(st + doff,          arow  + k0 + cchunk * 4, asz);
            cpa  (st + 16384u + doff, b0row + k0 + cchunk * 4);
            cpa  (st + 32768u + doff, b1row + k0 + cchunk * 4);
        }
    };

    float acc0[4][4][4] = {}, acc1[4][4][4] = {};

    auto compute = [&](int s) {
        const uint32_t st  = sb + (uint32_t)s * 49152u;
        const uint32_t ab  = st + aLane;
        const uint32_t b0b = st + 16384u + bLane;
        const uint32_t b1b = st + 32768u + bLane;
#pragma unroll
        for (int ks = 0; ks < 4; ks++) {
            const int kc = ks * 2;
            const uint32_t ca = (uint32_t)(((kc + c4a) ^ l7) << 4);
            const uint32_t cb = (uint32_t)(((kc + c4b) ^ l7) << 4);
            uint32_t af[4][4];
#pragma unroll
            for (int i = 0; i < 4; i++) ldsm4(af[i], ab + i * 2048 + ca);
#pragma unroll
            for (int jp = 0; jp < 2; jp++) {
                uint32_t f0[4], f1[4];
                ldsm4(f0, b0b + jp * 2048 + cb);
                ldsm4(f1, b1b + jp * 2048 + cb);
#pragma unroll
                for (int i = 0; i < 4; i++) {
                    mma8(acc0[i][jp * 2 + 0], af[i], f0 + 0);
                    mma8(acc0[i][jp * 2 + 1], af[i], f0 + 2);
                    mma8(acc1[i][jp * 2 + 0], af[i], f1 + 0);
                    mma8(acc1[i][jp * 2 + 1], af[i], f1 + 2);
                }
            }
        }
    };

    const int C = HID / 32;   // 32 chunks
    issue_stage(0, 0);  CP_COMMIT();
    issue_stage(1, 32); CP_COMMIT();
    for (int c = 0; c < C; c++) {
        CP_WAIT1();
        __syncthreads();
        compute(c % 3);
        if (c + 2 < C) issue_stage((c + 2) % 3, (c + 2) * 32);
        CP_COMMIT();
    }

    // epilogue: tf32-rounded silu(h0) * h1 -> g_inter (bit-identical to cvt-on-read)
#pragma unroll
    for (int i = 0; i < 4; i++) {
#pragma unroll
        for (int h = 0; h < 2; h++) {
            int m = m0 + wm * 64 + i * 16 + gq + h * 8;
            if (m >= cnt) continue;
            int entry = g_pairs[e * NPAIRS + m];
            float* orow = g_inter + (size_t)entry * INTER + n0 + wn * 32;
#pragma unroll
            for (int j = 0; j < 4; j++) {
                float h0a = acc0[i][j][h * 2 + 0], h0b = acc0[i][j][h * 2 + 1];
                float h1a = acc1[i][j][h * 2 + 0], h1b = acc1[i][j][h * 2 + 1];
                float oa = tf(h0a / (1.0f + __expf(-h0a)) * h1a);
                float ob = tf(h0b / (1.0f + __expf(-h0b)) * h1b);
                *(float2*)(orow + j * 8 + tg * 2) = make_float2(oa, ob);
            }
        }
    }
}

// ---------------- GEMM2: inter @ wo[e], fused weighted combine -------------------
// CTA 128M x 128N; 3-stage cp.async; 2 CTAs/SM target. Stage s: A @ s*32768, B @ +16384.
__global__ __launch_bounds__(256, 2) void gemm2_mma(float* __restrict__ out)
{
    const int e   = blockIdx.z;
    const int cnt = g_counts[e];
    const int m0  = blockIdx.y * 128;
    if (m0 >= cnt) return;
    const int n0  = blockIdx.x * 128;

    extern __shared__ float smf[];
    unsigned char* smc = (unsigned char*)smf;
    const uint32_t sb = smem_u32(smc);

    const int tid = threadIdx.x, lane = tid & 31, wid = tid >> 5;
    const int wm = wid >> 2, wn = wid & 3;
    const int gq = lane >> 2, tg = lane & 3;
    const int l7 = lane & 7;

    const uint32_t aLane = (uint32_t)(wm * 64 + l7 + ((lane >> 3) & 1) * 8) * 128u;
    const int      c4a   = lane >> 4;
    const uint32_t bLane = (uint32_t)(wn * 32 + ((lane >> 4) & 1) * 8 + l7) * 128u;
    const int      c4b   = (lane >> 3) & 1;

    const int row = tid >> 1, half = tid & 1;
    const float* arow;
    uint32_t asz;
    {
        int mg = m0 + row;
        if (mg < cnt) { arow = g_inter + (size_t)g_pairs[e * NPAIRS + mg] * INTER; asz = 16u; }
        else          { arow = g_inter; asz = 0u; }
    }
    const float* brow = g_wot + (size_t)e * HID * INTER + (size_t)(n0 + row) * INTER;

    const uint32_t dBase = (uint32_t)row * 128u;

    auto issue_stage = [&](int s, int k0) {
        const uint32_t st = sb + (uint32_t)s * 32768u;
#pragma unroll
        for (int q = 0; q < 4; q++) {
            int cchunk = half * 4 + q;
            uint32_t doff = dBase + (uint32_t)((cchunk ^ (row & 7)) << 4);
            cpa_z(st + doff,          arow + k0 + cchunk * 4, asz);
            cpa  (st + 16384u + doff, brow + k0 + cchunk * 4);
        }
    };

    float acc[4][4][4] = {};

    auto compute = [&](int s) {
        const uint32_t st = sb + (uint32_t)s * 32768u;
        const uint32_t ab = st + aLane;
        const uint32_t bb = st + 16384u + bLane;
#pragma unroll
        for (int ks = 0; ks < 4; ks++) {
            const int kc = ks * 2;
            const uint32_t ca = (uint32_t)(((kc + c4a) ^ l7) << 4);
            const uint32_t cb = (uint32_t)(((kc + c4b) ^ l7) << 4);
            uint32_t af[4][4];
#pragma unroll
            for (int i = 0; i < 4; i++) ldsm4(af[i], ab + i * 2048 + ca);
#pragma unroll
            for (int jp = 0; jp < 2; jp++) {
                uint32_t bf[4];
                ldsm4(bf, bb + jp * 2048 + cb);
#pragma unroll
                for (int i = 0; i < 4; i++) {
                    mma8(acc[i][jp * 2 + 0], af[i], bf + 0);
                    mma8(acc[i][jp * 2 + 1], af[i], bf + 2);
                }
            }
        }
    };

    const int C = INTER / 32;   // 64 chunks
    issue_stage(0, 0);  CP_COMMIT();
    issue_stage(1, 32); CP_COMMIT();
    for (int c = 0; c < C; c++) {
        CP_WAIT1();
        __syncthreads();
        compute(c % 3);
        if (c + 2 < C) issue_stage((c + 2) % 3, (c + 2) * 32);
        CP_COMMIT();
    }

    // fused combine: out[token] += w * y  (bitwise deterministic)
#pragma unroll
    for (int i = 0; i < 4; i++) {
#pragma unroll
        for (int h = 0; h < 2; h++) {
            int m = m0 + wm * 64 + i * 16 + gq + h * 8;
            if (m >= cnt) continue;
            int entry = g_pairs[e * NPAIRS + m];
            float w = g_w[entry];
            float* base = out + (size_t)(entry >> 1) * HID + n0 + wn * 32 + tg * 2;
#pragma unroll
            for (int j = 0; j < 4; j++) {
                atomicAdd(base + j * 8 + 0, w * acc[i][j][h * 2 + 0]);
                atomicAdd(base + j * 8 + 1, w * acc[i][j][h * 2 + 1]);
            }
        }
    }
}

// ---------------- launch -------------------------------------------------------------
extern "C" void kernel_launch(void* const* d_in, const int* in_sizes, int n_in,
                              void* d_out, int out_size)
{
    const float* x      = (const float*)d_in[0];
    const float* logits = (const float*)d_in[1];
    const float* wi0    = (const float*)d_in[2];
    const float* wi1    = (const float*)d_in[3];
    const float* wo     = (const float*)d_in[4];
    float* out          = (float*)d_out;

    const int g1_smem = 3 * 49152;   // 147456
    const int g2_smem = 3 * 32768;   // 98304
    cudaFuncSetAttribute(gemm1_mma, cudaFuncAttributeMaxDynamicSharedMemorySize, g1_smem);
    cudaFuncSetAttribute(gemm2_mma, cudaFuncAttributeMaxDynamicSharedMemorySize, g2_smem);

    zero_counts_kernel<<<1, 32>>>();
    route_kernel<<<T_TOKENS / 256, 256>>>(logits);
    zero_out_kernel<<<(T_TOKENS * HID / 4) / 256, 256>>>(out);

    // pre-pass: tf32 conversion (+ weight transpose to [n][k])
    convert_x_kernel<<<(T_TOKENS * HID / 4) / 256, 256>>>(x);
    {
        float* w0t; cudaGetSymbolAddress((void**)&w0t, g_w0t);
        float* w1t; cudaGetSymbolAddress((void**)&w1t, g_w1t);
        float* wot; cudaGetSymbolAddress((void**)&wot, g_wot);
        dim3 blk(32, 8);
        dim3 gwi(INTER / 32, HID / 32, NEXP);   // wi: [1024][2048] -> [2048][1024]
        tconv_kernel<<<gwi, blk>>>(wi0, w0t, HID, INTER);
        tconv_kernel<<<gwi, blk>>>(wi1, w1t, HID, INTER);
        dim3 gwo(HID / 32, INTER / 32, NEXP);   // wo: [2048][1024] -> [1024][2048]
        tconv_kernel<<<gwo, blk>>>(wo, wot, INTER, HID);
    }

    dim3 g1(INTER / 128, NPAIRS / 128, NEXP);   // (16, 32, 8)
    gemm1_mma<<<g1, 256, g1_smem>>>(x);

    dim3 g2(HID / 128, NPAIRS / 128, NEXP);     // (8, 32, 8)
    gemm2_mma<<<g2, 256, g2_smem>>>(out);
}